// round 17
// baseline (speedup 1.0000x reference)
#include <cuda_runtime.h>
#include <cuda_bf16.h>
#include <cstdint>
#include <cstddef>

#define S_LEN 4096
#define BATCH 8
#define DH    512
#define DIN   2048
#define M_TOT (S_LEN * BATCH)
#define CLUSTER 16

// bf16 hi/lo operand arrays (GEMM phase, unchanged)
__device__ __nv_bfloat16 g_xh[(size_t)M_TOT * DIN], g_xl[(size_t)M_TOT * DIN];
__device__ __nv_bfloat16 g_w1h[DH * DIN], g_w1l[DH * DIN];
__device__ __nv_bfloat16 g_seqh[(size_t)M_TOT * DH], g_seql[(size_t)M_TOT * DH];
__device__ __nv_bfloat16 g_w2h[3 * DH * DH], g_w2l[3 * DH * DH];
__device__ float g_G[(size_t)M_TOT * 3 * DH];

__device__ __forceinline__ uint32_t pack_split2(float x, float y, uint32_t& lo) {
    __nv_bfloat16 hx = __float2bfloat16(x), hy = __float2bfloat16(y);
    __nv_bfloat16 lx = __float2bfloat16(x - __bfloat162float(hx));
    __nv_bfloat16 ly = __float2bfloat16(y - __bfloat162float(hy));
    lo = ((uint32_t)__bfloat16_as_ushort(ly) << 16) | __bfloat16_as_ushort(lx);
    return ((uint32_t)__bfloat16_as_ushort(hy) << 16) | __bfloat16_as_ushort(hx);
}
__device__ __forceinline__ void split_store4(float4 v, __nv_bfloat16* ph, __nv_bfloat16* pl) {
    uint2 h, l;
    h.x = pack_split2(v.x, v.y, l.x);
    h.y = pack_split2(v.z, v.w, l.y);
    *reinterpret_cast<uint2*>(ph) = h;
    *reinterpret_cast<uint2*>(pl) = l;
}

__global__ __launch_bounds__(256) void cvt_x(const float* __restrict__ x) {
    size_t i4 = (size_t)blockIdx.x * 256 + threadIdx.x;
    int m = (int)(i4 >> 9), kq = (int)(i4 & 511);
    int b = m & 7, t = m >> 3;
    float4 v = reinterpret_cast<const float4*>(x)[((size_t)b * S_LEN + t) * 512 + kq];
    size_t o = (size_t)m * DIN + kq * 4;
    split_store4(v, g_xh + o, g_xl + o);
}
__global__ __launch_bounds__(256) void cvt_w1(const float* __restrict__ Wlm) {
    int i4 = blockIdx.x * 256 + threadIdx.x;
    float4 v = reinterpret_cast<const float4*>(Wlm)[i4];
    size_t o = (size_t)i4 * 4;
    split_store4(v, g_w1h + o, g_w1l + o);
}
__global__ __launch_bounds__(256) void cvt_w2(const float* __restrict__ Wz,
                                              const float* __restrict__ Wr,
                                              const float* __restrict__ Wh) {
    int i4 = blockIdx.x * 256 + threadIdx.x;
    int n = i4 >> 7, kq = i4 & 127;
    const float* W = (n < 512) ? Wz : (n < 1024) ? Wr : Wh;
    float4 v = reinterpret_cast<const float4*>(W + (size_t)(n & 511) * 1024)[kq];
    size_t o = (size_t)n * DH + kq * 4;
    split_store4(v, g_w2h + o, g_w2l + o);
}

// ---------------- bf16x3 tensor-core GEMM (unchanged) ----------------
__device__ __forceinline__ void cp16(uint32_t dst, const void* src) {
    asm volatile("cp.async.cg.shared.global [%0], [%1], 16;" :: "r"(dst), "l"(src));
}
#define MMA_BF16(c, a0, a1, a2, a3, b0, b1) \
    asm volatile("mma.sync.aligned.m16n8k16.row.col.f32.bf16.bf16.f32 " \
        "{%0,%1,%2,%3}, {%4,%5,%6,%7}, {%8,%9}, {%0,%1,%2,%3};" \
        : "+f"((c)[0]), "+f"((c)[1]), "+f"((c)[2]), "+f"((c)[3]) \
        : "r"(a0), "r"(a1), "r"(a2), "r"(a3), "r"(b0), "r"(b1))

__global__ __launch_bounds__(256) void mma_gemm(
    const __nv_bfloat16* __restrict__ Ah, const __nv_bfloat16* __restrict__ Al,
    const __nv_bfloat16* __restrict__ Bh, const __nv_bfloat16* __restrict__ Bl,
    float* __restrict__ Cf, __nv_bfloat16* __restrict__ Ch, __nv_bfloat16* __restrict__ Cl,
    int K, int N)
{
    extern __shared__ uint32_t sw[];
    const int tid = threadIdx.x;
    const int m0 = blockIdx.y * 128, n0 = blockIdx.x * 128;
    const int w = tid >> 5, l = tid & 31;
    const int wm = (w >> 2) * 64, wn = (w & 3) * 32;
    const int lq = l >> 2, lr = l & 3;
    const int row = tid >> 1, half = tid & 1;
    const uint32_t sbase = (uint32_t)__cvta_generic_to_shared(sw);
    const int NK = K >> 4;

    float acc[4][4][4];
#pragma unroll
    for (int a = 0; a < 4; a++)
#pragma unroll
        for (int b = 0; b < 4; b++)
#pragma unroll
            for (int c = 0; c < 4; c++) acc[a][b][c] = 0.f;

    const size_t arow = (size_t)(m0 + row) * K + half * 8;
    const size_t brow = (size_t)(n0 + row) * K + half * 8;
    {
        uint32_t d = sbase + (row * 12 + half * 4) * 4;
        cp16(d,         Ah + arow);
        cp16(d + 6144,  Al + arow);
        cp16(d + 12288, Bh + brow);
        cp16(d + 18432, Bl + brow);
        asm volatile("cp.async.commit_group;" ::: "memory");
    }
    for (int i = 0; i < NK; i++) {
        asm volatile("cp.async.wait_group 0;" ::: "memory");
        __syncthreads();
        const int st = i & 1;
        if (i + 1 < NK) {
            const int k0 = (i + 1) << 4;
            uint32_t d = sbase + ((st ^ 1) * 6144 + row * 12 + half * 4) * 4;
            cp16(d,         Ah + arow + k0);
            cp16(d + 6144,  Al + arow + k0);
            cp16(d + 12288, Bh + brow + k0);
            cp16(d + 18432, Bl + brow + k0);
            asm volatile("cp.async.commit_group;" ::: "memory");
        }
        const uint32_t* S = sw + st * 6144;
        uint32_t bh0[4], bh1[4], bl0[4], bl1[4];
#pragma unroll
        for (int nt = 0; nt < 4; nt++) {
            int o = 3072 + (wn + nt * 8 + lq) * 12 + lr;
            bh0[nt] = S[o]; bh1[nt] = S[o + 4];
            bl0[nt] = S[o + 1536]; bl1[nt] = S[o + 1540];
        }
#pragma unroll
        for (int mt = 0; mt < 4; mt++) {
            int m = wm + mt * 16 + lq;
            int o1 = m * 12 + lr, o2 = (m + 8) * 12 + lr;
            uint32_t ah0 = S[o1], ah1 = S[o2], ah2 = S[o1 + 4], ah3 = S[o2 + 4];
            uint32_t al0 = S[o1 + 1536], al1 = S[o2 + 1536];
            uint32_t al2 = S[o1 + 1540], al3 = S[o2 + 1540];
#pragma unroll
            for (int nt = 0; nt < 4; nt++) {
                MMA_BF16(acc[mt][nt], ah0, ah1, ah2, ah3, bh0[nt], bh1[nt]);
                MMA_BF16(acc[mt][nt], ah0, ah1, ah2, ah3, bl0[nt], bl1[nt]);
                MMA_BF16(acc[mt][nt], al0, al1, al2, al3, bh0[nt], bh1[nt]);
            }
        }
    }
#pragma unroll
    for (int mt = 0; mt < 4; mt++) {
#pragma unroll
        for (int nt = 0; nt < 4; nt++) {
            int m = m0 + wm + mt * 16 + lq;
            int c = n0 + wn + nt * 8 + lr * 2;
            const float* a = acc[mt][nt];
            if (Cf) {
                *reinterpret_cast<float2*>(Cf + (size_t)m * N + c)       = make_float2(a[0], a[1]);
                *reinterpret_cast<float2*>(Cf + (size_t)(m + 8) * N + c) = make_float2(a[2], a[3]);
            } else {
                uint32_t lo0, lo1;
                uint32_t hi0 = pack_split2(a[0], a[1], lo0);
                uint32_t hi1 = pack_split2(a[2], a[3], lo1);
                *reinterpret_cast<uint32_t*>(Ch + (size_t)m * N + c)       = hi0;
                *reinterpret_cast<uint32_t*>(Cl + (size_t)m * N + c)       = lo0;
                *reinterpret_cast<uint32_t*>(Ch + (size_t)(m + 8) * N + c) = hi1;
                *reinterpret_cast<uint32_t*>(Cl + (size_t)(m + 8) * N + c) = lo1;
            }
        }
    }
}

// ================= cluster / mbarrier / f32x2 helpers =================
__device__ __forceinline__ uint32_t smem_u32(const void* p) {
    return (uint32_t)__cvta_generic_to_shared(p);
}
__device__ __forceinline__ uint32_t dsmem_map(uint32_t a, unsigned r) {
    uint32_t x; asm("mapa.shared::cluster.u32 %0, %1, %2;" : "=r"(x) : "r"(a), "r"(r)); return x;
}
__device__ __forceinline__ void st_async32(uint32_t a, uint32_t mbar, float x) {
    asm volatile("st.async.shared::cluster.mbarrier::complete_tx::bytes.b32 [%0], %1, [%2];"
                 :: "r"(a), "r"(__float_as_uint(x)), "r"(mbar) : "memory");
}
__device__ __forceinline__ void st_async_u64(uint32_t a, uint32_t mbar, unsigned long long v) {
    asm volatile("st.async.shared::cluster.mbarrier::complete_tx::bytes.u64 [%0], %1, [%2];"
                 :: "r"(a), "l"(v), "r"(mbar) : "memory");
}
__device__ __forceinline__ void mbar_init(uint32_t a, uint32_t cnt) {
    asm volatile("mbarrier.init.shared.b64 [%0], %1;" :: "r"(a), "r"(cnt) : "memory");
}
__device__ __forceinline__ void mbar_expect_tx(uint32_t a, uint32_t tx) {
    asm volatile("mbarrier.arrive.expect_tx.shared.b64 _, [%0], %1;" :: "r"(a), "r"(tx) : "memory");
}
__device__ __forceinline__ void mbar_wait(uint32_t a, uint32_t parity) {
    uint32_t done;
    asm volatile("{\n\t.reg .pred p;\n\t"
                 "mbarrier.try_wait.parity.shared.b64 p, [%1], %2, 0x989680;\n\t"
                 "selp.b32 %0, 1, 0, p;\n\t}"
                 : "=r"(done) : "r"(a), "r"(parity) : "memory");
    while (!done) {
        asm volatile("{\n\t.reg .pred p;\n\t"
                     "mbarrier.try_wait.parity.shared.b64 p, [%1], %2, 0x989680;\n\t"
                     "selp.b32 %0, 1, 0, p;\n\t}"
                     : "=r"(done) : "r"(a), "r"(parity) : "memory");
    }
}
__device__ __forceinline__ void cl_sync() {
    asm volatile("barrier.cluster.arrive.aligned;" ::: "memory");
    asm volatile("barrier.cluster.wait.aligned;"   ::: "memory");
}
__device__ __forceinline__ float sigmoidf_(float v) { return 1.f / (1.f + __expf(-v)); }
__device__ __forceinline__ float tanh_fast(float v) {
    float y; asm("tanh.approx.f32 %0, %1;" : "=f"(y) : "f"(v)); return y;
}
__device__ __forceinline__ unsigned long long f2pack(float x, float y) {
    unsigned long long r; asm("mov.b64 %0, {%1,%2};" : "=l"(r) : "f"(x), "f"(y)); return r;
}
__device__ __forceinline__ void f2unpack(unsigned long long v, float& x, float& y) {
    asm("mov.b64 {%0,%1}, %2;" : "=f"(x), "=f"(y) : "l"(v));
}
__device__ __forceinline__ void fma2(unsigned long long& a, unsigned long long b,
                                     unsigned long long c) {
    asm("fma.rn.f32x2 %0, %1, %2, %0;" : "+l"(a) : "l"(b), "l"(c));
}
__device__ __forceinline__ void add2(unsigned long long& a, unsigned long long b) {
    asm("add.rn.f32x2 %0, %1, %2;" : "=l"(a) : "l"(a), "l"(b));
}

// ==== k-sliced GRU v3: ONE batch per cluster; 8 clusters x 16 CTAs x 512 thr ===
// CTA rank c owns h rows [32c,32c+32) and k-slice [32c,32c+32). Thread tid owns
// global row tid; z/r weights packed {wz,wr} in 32 u64 registers; wh in smem.
// Per step: p1 packed partial -> one u64 push -> owner warp0 sums/gates/forms
// r*h locally -> sync -> p2 scalar partial -> b32 push -> owner tanh + h
// update locally -> sync.  pz/phh single-buffered (safety chain as R14/R15).
// smem floats: whT[32][512]@0 | pz[16][32][2]@16384 | phh[16][32]@17408
//   hloc[32]@17920 | rhloc[32]@17952 | pcls[16][10]@17984 | mbars@18144
__global__ void __cluster_dims__(CLUSTER, 1, 1) __launch_bounds__(512, 1)
gru_kernel(const float* __restrict__ Wz, const float* __restrict__ Wr,
           const float* __restrict__ Wh, const float* __restrict__ Wc,
           float* __restrict__ out) {
    extern __shared__ float sm[];
    float* whT   = sm;
    float* pz    = sm + 16384;
    float* phh   = sm + 17408;
    float* hloc  = sm + 17920;
    float* rhloc = sm + 17952;
    float* pcls  = sm + 17984;
    const uint32_t mbb = smem_u32(sm + 18144);
    const uint32_t mb_pz = mbb, mb_ph = mbb + 8, mb_cls = mbb + 16;

    const int tid = threadIdx.x;
    unsigned rank; asm("mov.u32 %0, %%cluster_ctarank;" : "=r"(rank));
    const int b = blockIdx.x / CLUSTER;            // this cluster's batch
    const int j0 = (int)rank * 32;
    const int w = tid >> 5, l = tid & 31;

    // wh (phase-2) weights smem-transposed: whT[kl*512 + row]
    for (int i = tid; i < 16384; i += 512) {
        int kl = i >> 9, row = i & 511;
        whT[i] = Wh[(size_t)row * 1024 + 512 + j0 + kl];
    }
    // z/r weights register-resident, packed {wz, wr} per k (row = tid)
    unsigned long long wzr[32];
#pragma unroll
    for (int kl = 0; kl < 32; kl++) {
        float wzv = Wz[(size_t)tid * 1024 + 512 + j0 + kl];
        float wrv = Wr[(size_t)tid * 1024 + 512 + j0 + kl];
        wzr[kl] = f2pack(wzv, wrv);
    }
    if (tid < 32) hloc[tid] = 0.f;
    if (tid == 0) { mbar_init(mb_pz, 1); mbar_init(mb_ph, 1); mbar_init(mb_cls, 1); }
    __syncthreads();

    // push endpoints (dest rank = w; slot = my rank, local row l)
    const uint32_t pz_dst = dsmem_map(smem_u32(&pz[((int)rank * 32 + l) * 2]), (unsigned)w);
    const uint32_t ph_dst = dsmem_map(smem_u32(&phh[(int)rank * 32 + l]), (unsigned)w);
    const uint32_t mpz_r  = dsmem_map(mb_pz, (unsigned)w);
    const uint32_t mph_r  = dsmem_map(mb_ph, (unsigned)w);

    cl_sync();                                     // mbars + weights + h0 live

    // owner prefetch (warp 0, lane l = local row)
    float gxz = 0.f, gxr = 0.f, gxh = 0.f, zown = 0.f;
    if (w == 0) {
        const size_t gb = (size_t)b * 1536;
        gxz = g_G[gb + j0 + l];
        gxr = g_G[gb + 512 + j0 + l];
        gxh = g_G[gb + 1024 + j0 + l];
    }

    uint32_t phs = 0;
    for (int t = 0; t < S_LEN; t++) {
        if (tid == 0) {
            mbar_expect_tx(mb_pz, 4096);           // 16 src x 32 rows x 8B
            mbar_expect_tx(mb_ph, 2048);           // 16 src x 32 rows x 4B
        }
        const int tn = (t + 1 < S_LEN) ? t + 1 : t;

        // ---- phase 1: packed {z,r} partial for global row tid, one push ----
        unsigned long long acc = 0ULL;
#pragma unroll
        for (int kl = 0; kl < 32; kl++) {
            float h = hloc[kl];
            fma2(acc, wzr[kl], f2pack(h, h));
        }
        st_async_u64(pz_dst, mpz_r, acc);

        if (w == 0) {                              // owner: sum + gates + r*h
            mbar_wait(mb_pz, phs);
            unsigned long long s = 0ULL;
#pragma unroll
            for (int src = 0; src < 16; src++)
                add2(s, *(const unsigned long long*)&pz[(src * 32 + l) * 2]);
            float zs, rs; f2unpack(s, zs, rs);
            zown = sigmoidf_(zs + gxz);
            float r = sigmoidf_(rs + gxr);
            rhloc[l] = r * hloc[l];
            const size_t gbn = ((size_t)tn * 8 + b) * 1536;
            gxz = g_G[gbn + j0 + l];
            gxr = g_G[gbn + 512 + j0 + l];
        }
        __syncthreads();                           // rhloc ready

        // ---- phase 2: scalar h' partial over local r*h slice ----
        float accH = 0.f;
#pragma unroll
        for (int kl = 0; kl < 32; kl++)
            accH = fmaf(whT[kl * 512 + tid], rhloc[kl], accH);
        st_async32(ph_dst, mph_r, accH);

        if (w == 0) {                              // owner: sum + tanh + update
            mbar_wait(mb_ph, phs);
            float s = 0.f;
#pragma unroll
            for (int src = 0; src < 16; src++)
                s += phh[src * 32 + l];
            float hc = tanh_fast(s + gxh);
            float hold = hloc[l];
            hloc[l] = hold + zown * (hc - hold);
            gxh = g_G[((size_t)tn * 8 + b) * 1536 + 1024 + j0 + l];
        }
        __syncthreads();                           // hloc updated
        phs ^= 1;
    }

    // ---- classifier: per-CTA partials over its 32 h rows -> gather at rank 0 --
    if (rank == 0 && tid == 0) mbar_expect_tx(mb_cls, 640);   // 16 x 10 x 4B
    if (tid < 10) {
        float s = 0.f;
        for (int r2 = 0; r2 < 32; r2++)
            s += hloc[r2] * Wc[(size_t)tid * 512 + j0 + r2];
        uint32_t dst = dsmem_map(smem_u32(&pcls[rank * 10 + tid]), 0u);
        uint32_t mdst = dsmem_map(mb_cls, 0u);
        st_async32(dst, mdst, s);
    }
    if (rank == 0 && tid < 10) {
        mbar_wait(mb_cls, 0);
        float s = 0.f;
#pragma unroll
        for (int src = 0; src < 16; src++) s += pcls[src * 10 + tid];
        out[b * 10 + tid] = s;
    }
    cl_sync();                                     // no early-exit vs peer DSMEM
}

extern "C" void kernel_launch(void* const* d_in, const int* in_sizes, int n_in,
                              void* d_out, int out_size) {
    const float* x   = (const float*)d_in[0];
    const float* Wlm = (const float*)d_in[1];
    const float* Wz  = (const float*)d_in[2];
    const float* Wr  = (const float*)d_in[3];
    const float* Wh  = (const float*)d_in[4];
    const float* Wc  = (const float*)d_in[5];
    float* out = (float*)d_out;

    const int gemm_smem = 49152;
    const int gru_smem = 18152 * 4 + 32;           // ~73 KB
    cudaFuncSetAttribute(mma_gemm, cudaFuncAttributeMaxDynamicSharedMemorySize, gemm_smem);
    cudaFuncSetAttribute(gru_kernel, cudaFuncAttributeNonPortableClusterSizeAllowed, 1);
    cudaFuncSetAttribute(gru_kernel, cudaFuncAttributeMaxDynamicSharedMemorySize, gru_smem);

    __nv_bfloat16 *xh, *xl, *w1h, *w1l, *sh, *sl, *w2h, *w2l;
    float* G;
    cudaGetSymbolAddress((void**)&xh, g_xh);   cudaGetSymbolAddress((void**)&xl, g_xl);
    cudaGetSymbolAddress((void**)&w1h, g_w1h); cudaGetSymbolAddress((void**)&w1l, g_w1l);
    cudaGetSymbolAddress((void**)&sh, g_seqh); cudaGetSymbolAddress((void**)&sl, g_seql);
    cudaGetSymbolAddress((void**)&w2h, g_w2h); cudaGetSymbolAddress((void**)&w2l, g_w2l);
    cudaGetSymbolAddress((void**)&G, g_G);

    cvt_x<<<65536, 256>>>(x);
    cvt_w1<<<1024, 256>>>(Wlm);
    cvt_w2<<<768, 256>>>(Wz, Wr, Wh);
    mma_gemm<<<dim3(4, 256), 256, gemm_smem>>>(xh, xl, w1h, w1l,
                                               nullptr, sh, sl, DIN, DH);
    mma_gemm<<<dim3(12, 256), 256, gemm_smem>>>(sh, sl, w2h, w2l,
                                                G, nullptr, nullptr, DH, 3 * DH);
    gru_kernel<<<BATCH * CLUSTER, 512, gru_smem>>>(Wz, Wr, Wh, Wc, out);
}